// round 1
// baseline (speedup 1.0000x reference)
#include <cuda_runtime.h>
#include <cuda_fp16.h>

// Problem constants
#define BB 4
#define CC 64
#define NN 4096
#define DD 8     // q/k dim = C/8
#define MR 80    // v rows padded: 64 v + 1 ones + 15 zeros (tile M by 16)
#define BM 128   // m-columns per CTA
#define BN 64    // n (reduction) tile

// Scratch (allocation-free: __device__ globals)
__device__ __half g_qt[BB * NN * DD];   // [b][n][8]  (row-major, 16B rows)
__device__ __half g_kt[BB * NN * DD];   // [b][m][8]
__device__ __half g_vp[BB * MR * NN];   // [b][r][n]  r<64: v, r=64: ones, 65..79: 0

// ---------------------------------------------------------------------------
// Projection kernel: q = Wq x, k = Wk x, v = Wv x  (fp32 math -> fp16 store)
// One thread per (b, n) column of x.
// ---------------------------------------------------------------------------
__global__ __launch_bounds__(256) void proj_kernel(
    const float* __restrict__ x,
    const float* __restrict__ Wq,
    const float* __restrict__ Wk,
    const float* __restrict__ Wv)
{
    __shared__ float wq_t[64][8];
    __shared__ float wk_t[64][8];
    __shared__ float wv_t[64][64];

    int tid = threadIdx.x;
    for (int i = tid; i < 512; i += 256) {
        int j = i >> 6, c = i & 63;
        wq_t[c][j] = Wq[i];
        wk_t[c][j] = Wk[i];
    }
    for (int i = tid; i < 4096; i += 256) {
        int o = i >> 6, c = i & 63;
        wv_t[c][o] = Wv[i];
    }
    __syncthreads();

    int gi = blockIdx.x * 256 + tid;      // 0 .. B*N-1
    int b = gi >> 12;
    int n = gi & (NN - 1);

    float qa[8], ka[8], va[64];
#pragma unroll
    for (int j = 0; j < 8; j++) { qa[j] = 0.f; ka[j] = 0.f; }
#pragma unroll
    for (int o = 0; o < 64; o++) va[o] = 0.f;

    const float* xb = x + (size_t)b * CC * NN + n;
#pragma unroll 4
    for (int c = 0; c < 64; c++) {
        float xv = xb[(size_t)c * NN];
#pragma unroll
        for (int j = 0; j < 8; j++) {
            qa[j] += wq_t[c][j] * xv;
            ka[j] += wk_t[c][j] * xv;
        }
#pragma unroll
        for (int o = 0; o < 64; o++) va[o] += wv_t[c][o] * xv;
    }

    // store q, k as 16B rows
    __half qh[8], kh[8];
#pragma unroll
    for (int j = 0; j < 8; j++) {
        qh[j] = __float2half_rn(qa[j]);
        kh[j] = __float2half_rn(ka[j]);
    }
    *(uint4*)(g_qt + (size_t)(b * NN + n) * 8) = *(uint4*)qh;
    *(uint4*)(g_kt + (size_t)(b * NN + n) * 8) = *(uint4*)kh;

    __half* vp = g_vp + (size_t)b * MR * NN + n;
#pragma unroll
    for (int o = 0; o < 64; o++) vp[(size_t)o * NN] = __float2half_rn(va[o]);
    vp[(size_t)64 * NN] = __float2half_rn(1.0f);     // ones row -> denominator
#pragma unroll
    for (int o = 65; o < MR; o++) vp[(size_t)o * NN] = __ushort_as_half(0);
}

// ---------------------------------------------------------------------------
// ldmatrix / mma helpers
// ---------------------------------------------------------------------------
__device__ __forceinline__ unsigned smem_u32(const void* p) {
    return (unsigned)__cvta_generic_to_shared(p);
}
__device__ __forceinline__ void ldm_x2(unsigned& r0, unsigned& r1, unsigned addr) {
    asm volatile("ldmatrix.sync.aligned.m8n8.x2.shared.b16 {%0,%1}, [%2];\n"
                 : "=r"(r0), "=r"(r1) : "r"(addr));
}
__device__ __forceinline__ void ldm_x4(unsigned& r0, unsigned& r1, unsigned& r2, unsigned& r3, unsigned addr) {
    asm volatile("ldmatrix.sync.aligned.m8n8.x4.shared.b16 {%0,%1,%2,%3}, [%4];\n"
                 : "=r"(r0), "=r"(r1), "=r"(r2), "=r"(r3) : "r"(addr));
}
__device__ __forceinline__ void ldm_x4_t(unsigned& r0, unsigned& r1, unsigned& r2, unsigned& r3, unsigned addr) {
    asm volatile("ldmatrix.sync.aligned.m8n8.x4.trans.shared.b16 {%0,%1,%2,%3}, [%4];\n"
                 : "=r"(r0), "=r"(r1), "=r"(r2), "=r"(r3) : "r"(addr));
}
__device__ __forceinline__ void mma_k8(float* c, unsigned a0, unsigned a1, unsigned b0) {
    asm volatile(
        "mma.sync.aligned.m16n8k8.row.col.f32.f16.f16.f32 "
        "{%0,%1,%2,%3}, {%4,%5}, {%6}, {%0,%1,%2,%3};\n"
        : "+f"(c[0]), "+f"(c[1]), "+f"(c[2]), "+f"(c[3])
        : "r"(a0), "r"(a1), "r"(b0));
}
__device__ __forceinline__ void mma_k16(float* c, unsigned a0, unsigned a1, unsigned a2, unsigned a3,
                                        unsigned b0, unsigned b1) {
    asm volatile(
        "mma.sync.aligned.m16n8k16.row.col.f32.f16.f16.f32 "
        "{%0,%1,%2,%3}, {%4,%5,%6,%7}, {%8,%9}, {%0,%1,%2,%3};\n"
        : "+f"(c[0]), "+f"(c[1]), "+f"(c[2]), "+f"(c[3])
        : "r"(a0), "r"(a1), "r"(a2), "r"(a3), "r"(b0), "r"(b1));
}

// ---------------------------------------------------------------------------
// Fused attention: per CTA = (batch b, 128 m-columns).
// S = q^T k_m  (m16n8k8), E = exp(S) fp16 in smem, O += V' @ E (m16n8k16).
// Row 64 of O is the softmax denominator (ones-row trick).
// No max-subtraction needed: |s| <= ~3 analytically.
// ---------------------------------------------------------------------------
__global__ __launch_bounds__(256) void attn_kernel(
    const float* __restrict__ x,
    const float* __restrict__ gamma,
    float* __restrict__ out)
{
    __shared__ __half k_s[BM][8];        // 2 KB
    __shared__ __half q_s[BN][8];        // 1 KB
    __shared__ __half v_s[MR][88];       // 14 KB  (stride 176B: 16B-aligned, conflict-free)
    __shared__ __half e_s[BN][136];      // 17 KB  (stride 272B: 16B-aligned, conflict-free)
    __shared__ float  d_s[BM];

    const int b  = blockIdx.y;
    const int m0 = blockIdx.x * BM;
    const int tid = threadIdx.x;
    const int w = tid >> 5, lane = tid & 31, g = lane >> 2, tc = lane & 3;

    // ---- load k tile for this CTA's 128 m-columns ----
    if (tid < BM)
        *(uint4*)&k_s[tid][0] = *(const uint4*)(g_kt + (size_t)(b * NN + m0 + tid) * 8);
    __syncthreads();

    // S-phase warp mapping: n-row tile = (w&3)*16, m-half = (w>>2)*64
    const int nw0 = (w & 3) * 16;
    const int mh0 = (w >> 2) * 64;

    // k fragments for this warp's 8 n8-tiles (resident whole kernel)
    unsigned kb[8];
    ldm_x4(kb[0], kb[1], kb[2], kb[3], smem_u32(&k_s[mh0 + lane][0]));
    ldm_x4(kb[4], kb[5], kb[6], kb[7], smem_u32(&k_s[mh0 + 32 + lane][0]));

    // PV accumulators: warp strip = m-cols [w*16, w*16+16), all 80 rows
    float O[5][2][4];
#pragma unroll
    for (int mt = 0; mt < 5; mt++)
#pragma unroll
        for (int nt = 0; nt < 2; nt++)
#pragma unroll
            for (int r = 0; r < 4; r++) O[mt][nt][r] = 0.f;

    const int ms0 = w * 16;
    const float L2E = 1.44269504f;

    for (int n0 = 0; n0 < NN; n0 += BN) {
        // ---- stage q tile + v tile ----
        if (tid < BN)
            *(uint4*)&q_s[tid][0] = *(const uint4*)(g_qt + (size_t)(b * NN + n0 + tid) * 8);
        for (int i = tid; i < MR * (BN / 8); i += 256) {    // 640 uint4
            int r = i >> 3, cs = (i & 7) * 8;
            *(uint4*)&v_s[r][cs] =
                *(const uint4*)(g_vp + (size_t)(b * MR + r) * NN + n0 + cs);
        }
        __syncthreads();

        // ---- S = q^T k : warp does 16 n-rows x 64 m-cols via 8 mma.k8 ----
        unsigned a0, a1;
        ldm_x2(a0, a1, smem_u32(&q_s[nw0 + (lane & 15)][0]));
        float sacc[8][4];
#pragma unroll
        for (int mt = 0; mt < 8; mt++) {
            sacc[mt][0] = 0.f; sacc[mt][1] = 0.f; sacc[mt][2] = 0.f; sacc[mt][3] = 0.f;
            mma_k8(sacc[mt], a0, a1, kb[mt]);
        }

        // ---- E = exp(S) -> fp16 smem (ex2.approx.f16x2: 2 exps / MUFU op) ----
#pragma unroll
        for (int mt = 0; mt < 8; mt++) {
            int col = mh0 + mt * 8 + tc * 2;
            __half2 h01 = __floats2half2_rn(sacc[mt][0] * L2E, sacc[mt][1] * L2E);
            __half2 h23 = __floats2half2_rn(sacc[mt][2] * L2E, sacc[mt][3] * L2E);
            unsigned e01, e23;
            asm volatile("ex2.approx.f16x2 %0, %1;\n" : "=r"(e01) : "r"(*(unsigned*)&h01));
            asm volatile("ex2.approx.f16x2 %0, %1;\n" : "=r"(e23) : "r"(*(unsigned*)&h23));
            *(unsigned*)&e_s[nw0 + g][col]     = e01;
            *(unsigned*)&e_s[nw0 + 8 + g][col] = e23;
        }
        __syncthreads();

        // ---- O += V'[80 x 64] @ E[64 x 128] : warp owns 16-wide m-strip ----
#pragma unroll
        for (int ks = 0; ks < BN / 16; ks++) {
            unsigned b0, b1, b2, b3;
            ldm_x4_t(b0, b1, b2, b3,
                     smem_u32(&e_s[ks * 16 + (lane & 15)][ms0 + 8 * (lane >> 4)]));
#pragma unroll
            for (int mt = 0; mt < 5; mt++) {
                unsigned v0, v1, v2, v3;
                ldm_x4(v0, v1, v2, v3,
                       smem_u32(&v_s[mt * 16 + (lane & 15)][ks * 16 + 8 * (lane >> 4)]));
                mma_k16(O[mt][0], v0, v1, v2, v3, b0, b1);
                mma_k16(O[mt][1], v0, v1, v2, v3, b2, b3);
            }
        }
        __syncthreads();
    }

    // ---- denominator broadcast (row 64 = Mtile 4, g==0, i==0) ----
    if (g == 0) {
#pragma unroll
        for (int nt = 0; nt < 2; nt++) {
            d_s[ms0 + nt * 8 + tc * 2]     = O[4][nt][0];
            d_s[ms0 + nt * 8 + tc * 2 + 1] = O[4][nt][1];
        }
    }
    __syncwarp();

    // ---- epilogue: out = gamma * O/denom + x ----
    const float gam = *gamma;
#pragma unroll
    for (int mt = 0; mt < 4; mt++) {
#pragma unroll
        for (int nt = 0; nt < 2; nt++) {
#pragma unroll
            for (int i = 0; i < 2; i++) {
                int row = mt * 16 + g + 8 * i;
                int col = ms0 + nt * 8 + tc * 2;
                size_t base = (size_t)(b * CC + row) * NN + m0 + col;
                float dn0 = d_s[col], dn1 = d_s[col + 1];
                out[base]     = gam * O[mt][nt][2 * i]     / dn0 + x[base];
                out[base + 1] = gam * O[mt][nt][2 * i + 1] / dn1 + x[base + 1];
            }
        }
    }
}

// ---------------------------------------------------------------------------
extern "C" void kernel_launch(void* const* d_in, const int* in_sizes, int n_in,
                              void* d_out, int out_size)
{
    const float* x     = (const float*)d_in[0];
    const float* Wq    = (const float*)d_in[1];
    const float* Wk    = (const float*)d_in[2];
    const float* Wv    = (const float*)d_in[3];
    const float* gamma = (const float*)d_in[4];
    float* out = (float*)d_out;

    proj_kernel<<<(BB * NN) / 256, 256>>>(x, Wq, Wk, Wv);
    attn_kernel<<<dim3(NN / BM, BB), 256>>>(x, gamma, out);
}

// round 3
// speedup vs baseline: 2.3806x; 2.3806x over previous
#include <cuda_runtime.h>
#include <cuda_fp16.h>

// Problem constants
#define BB 4
#define CC 64
#define NN 4096
#define DD 8     // q/k dim = C/8
#define MR 80    // v rows padded: 64 v + 1 ones + 15 zeros (tile M by 16)
#define BM 64    // m-columns per CTA
#define BN 64    // n (reduction) tile
#define NT (NN / BN)   // 64 n-tiles

// Scratch (allocation-free: __device__ globals)
__device__ __half g_qt[BB * NN * DD];   // [b][n][8]
__device__ __half g_kt[BB * NN * DD];   // [b][m][8]
__device__ __half g_vp[BB * MR * NN];   // [b][r][n]  r<64: v, r=64: ones, 65..79: 0

// ---------------------------------------------------------------------------
// Projection kernel: q = Wq x, k = Wk x, v = Wv x  (fp32 math -> fp16 store)
// 128 threads / CTA, 128 CTAs.
// ---------------------------------------------------------------------------
__global__ __launch_bounds__(128) void proj_kernel(
    const float* __restrict__ x,
    const float* __restrict__ Wq,
    const float* __restrict__ Wk,
    const float* __restrict__ Wv)
{
    __shared__ float wq_t[64][8];
    __shared__ float wk_t[64][8];
    __shared__ float wv_t[64][64];

    int tid = threadIdx.x;
    for (int i = tid; i < 512; i += 128) {
        int j = i >> 6, c = i & 63;
        wq_t[c][j] = Wq[i];
        wk_t[c][j] = Wk[i];
    }
    for (int i = tid; i < 4096; i += 128) {
        int o = i >> 6, c = i & 63;
        wv_t[c][o] = Wv[i];
    }
    __syncthreads();

    int gi = blockIdx.x * 128 + tid;      // 0 .. B*N-1
    int b = gi >> 12;
    int n = gi & (NN - 1);

    float qa[8], ka[8], va[64];
#pragma unroll
    for (int j = 0; j < 8; j++) { qa[j] = 0.f; ka[j] = 0.f; }
#pragma unroll
    for (int o = 0; o < 64; o++) va[o] = 0.f;

    const float* xb = x + (size_t)b * CC * NN + n;
#pragma unroll 4
    for (int c = 0; c < 64; c++) {
        float xv = xb[(size_t)c * NN];
#pragma unroll
        for (int j = 0; j < 8; j++) {
            qa[j] += wq_t[c][j] * xv;
            ka[j] += wk_t[c][j] * xv;
        }
#pragma unroll
        for (int o = 0; o < 64; o++) va[o] += wv_t[c][o] * xv;
    }

    __half qh[8], kh[8];
#pragma unroll
    for (int j = 0; j < 8; j++) {
        qh[j] = __float2half_rn(qa[j]);
        kh[j] = __float2half_rn(ka[j]);
    }
    *(uint4*)(g_qt + (size_t)(b * NN + n) * 8) = *(uint4*)qh;
    *(uint4*)(g_kt + (size_t)(b * NN + n) * 8) = *(uint4*)kh;

    __half* vp = g_vp + (size_t)b * MR * NN + n;
#pragma unroll
    for (int o = 0; o < 64; o++) vp[(size_t)o * NN] = __float2half_rn(va[o]);
    vp[(size_t)64 * NN] = __float2half_rn(1.0f);     // ones row -> denominator
#pragma unroll
    for (int o = 65; o < MR; o++) vp[(size_t)o * NN] = __ushort_as_half(0);
}

// ---------------------------------------------------------------------------
// helpers
// ---------------------------------------------------------------------------
__device__ __forceinline__ unsigned smem_u32(const void* p) {
    return (unsigned)__cvta_generic_to_shared(p);
}
__device__ __forceinline__ void cpa16(void* dst, const void* src) {
    asm volatile("cp.async.cg.shared.global [%0], [%1], 16;\n"
                 :: "r"(smem_u32(dst)), "l"(src));
}
__device__ __forceinline__ void cpa_commit() {
    asm volatile("cp.async.commit_group;\n");
}
template <int N>
__device__ __forceinline__ void cpa_wait() {
    asm volatile("cp.async.wait_group %0;\n" :: "n"(N));
}
__device__ __forceinline__ void ldm_x2(unsigned& r0, unsigned& r1, unsigned addr) {
    asm volatile("ldmatrix.sync.aligned.m8n8.x2.shared.b16 {%0,%1}, [%2];\n"
                 : "=r"(r0), "=r"(r1) : "r"(addr));
}
__device__ __forceinline__ void ldm_x4(unsigned& r0, unsigned& r1, unsigned& r2, unsigned& r3, unsigned addr) {
    asm volatile("ldmatrix.sync.aligned.m8n8.x4.shared.b16 {%0,%1,%2,%3}, [%4];\n"
                 : "=r"(r0), "=r"(r1), "=r"(r2), "=r"(r3) : "r"(addr));
}
__device__ __forceinline__ void ldm_x4_t(unsigned& r0, unsigned& r1, unsigned& r2, unsigned& r3, unsigned addr) {
    asm volatile("ldmatrix.sync.aligned.m8n8.x4.trans.shared.b16 {%0,%1,%2,%3}, [%4];\n"
                 : "=r"(r0), "=r"(r1), "=r"(r2), "=r"(r3) : "r"(addr));
}
__device__ __forceinline__ void mma_k8(float* c, unsigned a0, unsigned a1, unsigned b0) {
    asm volatile(
        "mma.sync.aligned.m16n8k8.row.col.f32.f16.f16.f32 "
        "{%0,%1,%2,%3}, {%4,%5}, {%6}, {%0,%1,%2,%3};\n"
        : "+f"(c[0]), "+f"(c[1]), "+f"(c[2]), "+f"(c[3])
        : "r"(a0), "r"(a1), "r"(b0));
}
__device__ __forceinline__ void mma_k16(float* c, unsigned a0, unsigned a1, unsigned a2, unsigned a3,
                                        unsigned b0, unsigned b1) {
    asm volatile(
        "mma.sync.aligned.m16n8k16.row.col.f32.f16.f16.f32 "
        "{%0,%1,%2,%3}, {%4,%5,%6,%7}, {%8,%9}, {%0,%1,%2,%3};\n"
        : "+f"(c[0]), "+f"(c[1]), "+f"(c[2]), "+f"(c[3])
        : "r"(a0), "r"(a1), "r"(a2), "r"(a3), "r"(b0), "r"(b1));
}

// ---------------------------------------------------------------------------
// Fused attention: per CTA = (batch b, 64 m-columns), 4 warps, 256 CTAs.
// Double-buffered q/v staging via cp.async.
// ---------------------------------------------------------------------------
__global__ __launch_bounds__(128, 5) void attn_kernel(
    const float* __restrict__ x,
    const float* __restrict__ gamma,
    float* __restrict__ out)
{
    __shared__ __half k_s[BM][8];            // 1 KB
    __shared__ __half q_s[2][BN][8];         // 2 KB
    __shared__ __half v_s[2][MR][72];        // 22.5 KB (stride 144B, odd 16B units: conflict-free)
    __shared__ __half e_s[BN][72];           // 9 KB
    __shared__ float  d_s[BM];

    const int b  = blockIdx.y;
    const int m0 = blockIdx.x * BM;
    const int tid = threadIdx.x;
    const int w = tid >> 5, lane = tid & 31, g = lane >> 2, tc = lane & 3;

    // ---- k tile for this CTA's 64 m-columns ----
    if (tid < BM)
        *(uint4*)&k_s[tid][0] = *(const uint4*)(g_kt + (size_t)(b * NN + m0 + tid) * 8);

    // ---- prefetch tile 0 (q + v) ----
    {
        if (tid < BN)
            cpa16(&q_s[0][tid][0], g_qt + (size_t)(b * NN + tid) * 8);
#pragma unroll
        for (int i = 0; i < 5; i++) {
            int e = tid + i * 128;                  // 0..639
            int r = e >> 3, cs = (e & 7) * 8;
            cpa16(&v_s[0][r][cs], g_vp + (size_t)(b * MR + r) * NN + cs);
        }
        cpa_commit();
    }
    __syncthreads();   // k_s ready

    // k fragments: all 64 m-cols (8 n8-tiles), resident whole kernel
    unsigned kb[8];
    ldm_x4(kb[0], kb[1], kb[2], kb[3], smem_u32(&k_s[lane][0]));
    ldm_x4(kb[4], kb[5], kb[6], kb[7], smem_u32(&k_s[32 + lane][0]));

    // PV accumulators: warp owns m-cols [w*16, w*16+16), all 80 rows
    float O[5][2][4];
#pragma unroll
    for (int mt = 0; mt < 5; mt++)
#pragma unroll
        for (int nt = 0; nt < 2; nt++)
#pragma unroll
            for (int r = 0; r < 4; r++) O[mt][nt][r] = 0.f;

    const int nw0 = w * 16;      // S-phase: warp's 16 n-rows
    const int ms0 = w * 16;      // PV-phase: warp's 16 m-cols
    const float L2E = 1.44269504f;

    for (int it = 0; it < NT; it++) {
        const int cur = it & 1;

        // ---- prefetch next tile ----
        if (it + 1 < NT) {
            const int nn = (it + 1) * BN;
            const int nxt = cur ^ 1;
            if (tid < BN)
                cpa16(&q_s[nxt][tid][0], g_qt + (size_t)(b * NN + nn + tid) * 8);
#pragma unroll
            for (int i = 0; i < 5; i++) {
                int e = tid + i * 128;
                int r = e >> 3, cs = (e & 7) * 8;
                cpa16(&v_s[nxt][r][cs], g_vp + (size_t)(b * MR + r) * NN + nn + cs);
            }
            cpa_commit();
            cpa_wait<1>();
        } else {
            cpa_wait<0>();
        }
        __syncthreads();  // current buffer ready; e_s free

        // ---- S = q^T k, fused exp -> e_s (warp: 16 n-rows x 64 m-cols) ----
        unsigned a0, a1;
        ldm_x2(a0, a1, smem_u32(&q_s[cur][nw0 + (lane & 15)][0]));
#pragma unroll
        for (int mt = 0; mt < 8; mt++) {
            float sacc[4] = {0.f, 0.f, 0.f, 0.f};
            mma_k8(sacc, a0, a1, kb[mt]);
            int col = mt * 8 + tc * 2;
            __half2 h01 = __floats2half2_rn(sacc[0] * L2E, sacc[1] * L2E);
            __half2 h23 = __floats2half2_rn(sacc[2] * L2E, sacc[3] * L2E);
            unsigned e01, e23;
            asm volatile("ex2.approx.f16x2 %0, %1;\n" : "=r"(e01) : "r"(*(unsigned*)&h01));
            asm volatile("ex2.approx.f16x2 %0, %1;\n" : "=r"(e23) : "r"(*(unsigned*)&h23));
            *(unsigned*)&e_s[nw0 + g][col]     = e01;
            *(unsigned*)&e_s[nw0 + 8 + g][col] = e23;
        }
        __syncthreads();  // e_s complete

        // ---- O += V'[80 x 64] @ E[64 x 64] : warp owns 16-wide m-strip ----
#pragma unroll
        for (int ks = 0; ks < BN / 16; ks++) {
            unsigned b0, b1, b2, b3;
            ldm_x4_t(b0, b1, b2, b3,
                     smem_u32(&e_s[ks * 16 + (lane & 15)][ms0 + 8 * (lane >> 4)]));
#pragma unroll
            for (int mt = 0; mt < 5; mt++) {
                unsigned v0, v1, v2, v3;
                ldm_x4(v0, v1, v2, v3,
                       smem_u32(&v_s[cur][mt * 16 + (lane & 15)][ks * 16 + 8 * (lane >> 4)]));
                mma_k16(O[mt][0], v0, v1, v2, v3, b0, b1);
                mma_k16(O[mt][1], v0, v1, v2, v3, b2, b3);
            }
        }
        __syncthreads();  // protect e_s (rewritten next iter)
    }

    // ---- denominator broadcast (row 64 = tile 4, g==0, i==0) ----
    if (g == 0) {
#pragma unroll
        for (int nt = 0; nt < 2; nt++) {
            d_s[ms0 + nt * 8 + tc * 2]     = O[4][nt][0];
            d_s[ms0 + nt * 8 + tc * 2 + 1] = O[4][nt][1];
        }
    }
    __syncwarp();

    // ---- epilogue: out = gamma * O/denom + x ----
    const float gam = *gamma;
#pragma unroll
    for (int mt = 0; mt < 4; mt++) {
#pragma unroll
        for (int nt = 0; nt < 2; nt++) {
#pragma unroll
            for (int i = 0; i < 2; i++) {
                int row = mt * 16 + g + 8 * i;
                int col = ms0 + nt * 8 + tc * 2;
                size_t base = (size_t)(b * CC + row) * NN + m0 + col;
                float dn0 = d_s[col], dn1 = d_s[col + 1];
                out[base]     = gam * O[mt][nt][2 * i]     / dn0 + x[base];
                out[base + 1] = gam * O[mt][nt][2 * i + 1] / dn1 + x[base + 1];
            }
        }
    }
}

// ---------------------------------------------------------------------------
extern "C" void kernel_launch(void* const* d_in, const int* in_sizes, int n_in,
                              void* d_out, int out_size)
{
    const float* x     = (const float*)d_in[0];
    const float* Wq    = (const float*)d_in[1];
    const float* Wk    = (const float*)d_in[2];
    const float* Wv    = (const float*)d_in[3];
    const float* gamma = (const float*)d_in[4];
    float* out = (float*)d_out;

    proj_kernel<<<(BB * NN) / 128, 128>>>(x, Wq, Wk, Wv);
    attn_kernel<<<dim3(NN / BM, BB), 128>>>(x, gamma, out);
}

// round 4
// speedup vs baseline: 2.3852x; 1.0019x over previous
#include <cuda_runtime.h>
#include <cuda_fp16.h>

// Problem constants
#define BB 4
#define CC 64
#define NN 4096
#define DD 8      // q/k dim = C/8
#define MR 80     // v rows padded: 64 v + 1 ones + 15 zeros (tile M by 16)
#define BM 32     // m-columns per CTA
#define NSPLIT 2  // split-K over the n (reduction) axis
#define NHALF (NN / NSPLIT)     // 2048
#define BN 64     // n tile
#define NT (NHALF / BN)         // 32 tiles per CTA

// Scratch (allocation-free: __device__ globals)
__device__ __half g_qt[BB * NN * DD];        // [b][n][8]
__device__ __half g_kt[BB * NN * DD];        // [b][m][8]
__device__ __half g_vp[BB * MR * NN];        // [b][r][n]
__device__ float  g_part[NSPLIT * BB * 65 * NN];  // partial O (+denom row 64), 8.5MB

// ---------------------------------------------------------------------------
// Projection kernel: q = Wq x, k = Wk x, v = Wv x
// ---------------------------------------------------------------------------
__global__ __launch_bounds__(128) void proj_kernel(
    const float* __restrict__ x,
    const float* __restrict__ Wq,
    const float* __restrict__ Wk,
    const float* __restrict__ Wv)
{
    __shared__ float wq_t[64][8];
    __shared__ float wk_t[64][8];
    __shared__ float wv_t[64][64];

    int tid = threadIdx.x;
    for (int i = tid; i < 512; i += 128) {
        int j = i >> 6, c = i & 63;
        wq_t[c][j] = Wq[i];
        wk_t[c][j] = Wk[i];
    }
    for (int i = tid; i < 4096; i += 128) {
        int o = i >> 6, c = i & 63;
        wv_t[c][o] = Wv[i];
    }
    __syncthreads();

    int gi = blockIdx.x * 128 + tid;
    int b = gi >> 12;
    int n = gi & (NN - 1);

    float qa[8], ka[8], va[64];
#pragma unroll
    for (int j = 0; j < 8; j++) { qa[j] = 0.f; ka[j] = 0.f; }
#pragma unroll
    for (int o = 0; o < 64; o++) va[o] = 0.f;

    const float* xb = x + (size_t)b * CC * NN + n;
#pragma unroll 4
    for (int c = 0; c < 64; c++) {
        float xv = xb[(size_t)c * NN];
#pragma unroll
        for (int j = 0; j < 8; j++) {
            qa[j] += wq_t[c][j] * xv;
            ka[j] += wk_t[c][j] * xv;
        }
#pragma unroll
        for (int o = 0; o < 64; o++) va[o] += wv_t[c][o] * xv;
    }

    __half qh[8], kh[8];
#pragma unroll
    for (int j = 0; j < 8; j++) {
        qh[j] = __float2half_rn(qa[j]);
        kh[j] = __float2half_rn(ka[j]);
    }
    *(uint4*)(g_qt + (size_t)(b * NN + n) * 8) = *(uint4*)qh;
    *(uint4*)(g_kt + (size_t)(b * NN + n) * 8) = *(uint4*)kh;

    __half* vp = g_vp + (size_t)b * MR * NN + n;
#pragma unroll
    for (int o = 0; o < 64; o++) vp[(size_t)o * NN] = __float2half_rn(va[o]);
    vp[(size_t)64 * NN] = __float2half_rn(1.0f);     // ones row -> denominator
#pragma unroll
    for (int o = 65; o < MR; o++) vp[(size_t)o * NN] = __ushort_as_half(0);
}

// ---------------------------------------------------------------------------
// helpers
// ---------------------------------------------------------------------------
__device__ __forceinline__ unsigned smem_u32(const void* p) {
    return (unsigned)__cvta_generic_to_shared(p);
}
__device__ __forceinline__ void cpa16(void* dst, const void* src) {
    asm volatile("cp.async.cg.shared.global [%0], [%1], 16;\n"
                 :: "r"(smem_u32(dst)), "l"(src));
}
__device__ __forceinline__ void cpa_commit() {
    asm volatile("cp.async.commit_group;\n");
}
template <int N>
__device__ __forceinline__ void cpa_wait() {
    asm volatile("cp.async.wait_group %0;\n" :: "n"(N));
}
__device__ __forceinline__ void ldm_x2(unsigned& r0, unsigned& r1, unsigned addr) {
    asm volatile("ldmatrix.sync.aligned.m8n8.x2.shared.b16 {%0,%1}, [%2];\n"
                 : "=r"(r0), "=r"(r1) : "r"(addr));
}
__device__ __forceinline__ void ldm_x2_t(unsigned& r0, unsigned& r1, unsigned addr) {
    asm volatile("ldmatrix.sync.aligned.m8n8.x2.trans.shared.b16 {%0,%1}, [%2];\n"
                 : "=r"(r0), "=r"(r1) : "r"(addr));
}
__device__ __forceinline__ void ldm_x4(unsigned& r0, unsigned& r1, unsigned& r2, unsigned& r3, unsigned addr) {
    asm volatile("ldmatrix.sync.aligned.m8n8.x4.shared.b16 {%0,%1,%2,%3}, [%4];\n"
                 : "=r"(r0), "=r"(r1), "=r"(r2), "=r"(r3) : "r"(addr));
}
__device__ __forceinline__ void mma_k8(float* c, unsigned a0, unsigned a1, unsigned b0) {
    asm volatile(
        "mma.sync.aligned.m16n8k8.row.col.f32.f16.f16.f32 "
        "{%0,%1,%2,%3}, {%4,%5}, {%6}, {%0,%1,%2,%3};\n"
        : "+f"(c[0]), "+f"(c[1]), "+f"(c[2]), "+f"(c[3])
        : "r"(a0), "r"(a1), "r"(b0));
}
__device__ __forceinline__ void mma_k16(float* c, unsigned a0, unsigned a1, unsigned a2, unsigned a3,
                                        unsigned b0, unsigned b1) {
    asm volatile(
        "mma.sync.aligned.m16n8k16.row.col.f32.f16.f16.f32 "
        "{%0,%1,%2,%3}, {%4,%5,%6,%7}, {%8,%9}, {%0,%1,%2,%3};\n"
        : "+f"(c[0]), "+f"(c[1]), "+f"(c[2]), "+f"(c[3])
        : "r"(a0), "r"(a1), "r"(a2), "r"(a3), "r"(b0), "r"(b1));
}

// ---------------------------------------------------------------------------
// Attention main: CTA = (m-strip of 32, batch, n-half). 4 warps, 1024 CTAs.
// Writes fp32 partial O (rows 0..63) + denominator (row 64) to g_part.
// ---------------------------------------------------------------------------
__global__ __launch_bounds__(128, 7) void attn_kernel()
{
    __shared__ __half k_s[BM][8];            // 0.5 KB
    __shared__ __half q_s[2][BN][8];         // 2 KB
    __shared__ __half v_s[2][MR][72];        // 22.5 KB (stride 144B: conflict-free)
    __shared__ __half e_s[BN][40];           // 5 KB   (stride 80B: 5r%8 conflict-free)

    const int b  = blockIdx.y;
    const int m0 = blockIdx.x * BM;
    const int sp = blockIdx.z;
    const int s0 = sp * NHALF;
    const int tid = threadIdx.x;
    const int w = tid >> 5, lane = tid & 31, g = lane >> 2, tc = lane & 3;

    // ---- k tile: this CTA's 32 m-columns ----
    if (tid < BM)
        *(uint4*)&k_s[tid][0] = *(const uint4*)(g_kt + (size_t)(b * NN + m0 + tid) * 8);

    // ---- prefetch tile 0 ----
    {
        if (tid < BN)
            cpa16(&q_s[0][tid][0], g_qt + (size_t)(b * NN + s0 + tid) * 8);
#pragma unroll
        for (int i = 0; i < 5; i++) {
            int e = tid + i * 128;                  // 0..639
            int r = e >> 3, cs = (e & 7) * 8;
            cpa16(&v_s[0][r][cs], g_vp + (size_t)(b * MR + r) * NN + s0 + cs);
        }
        cpa_commit();
    }
    __syncthreads();   // k_s ready

    // k fragments: 32 m-cols = 4 n8-tiles (resident whole kernel)
    unsigned kb[4];
    ldm_x4(kb[0], kb[1], kb[2], kb[3], smem_u32(&k_s[lane][0]));

    // PV accumulators: warp owns m-cols [w*8, w*8+8), all 80 rows
    float O[5][4];
#pragma unroll
    for (int mt = 0; mt < 5; mt++)
#pragma unroll
        for (int r = 0; r < 4; r++) O[mt][r] = 0.f;

    const int nw0 = w * 16;      // S-phase: warp's 16 n-rows
    const int ms0 = w * 8;       // PV-phase: warp's 8 m-cols
    const float L2E = 1.44269504f;

    for (int it = 0; it < NT; it++) {
        const int cur = it & 1;

        // ---- prefetch next tile ----
        if (it + 1 < NT) {
            const int nn = s0 + (it + 1) * BN;
            const int nxt = cur ^ 1;
            if (tid < BN)
                cpa16(&q_s[nxt][tid][0], g_qt + (size_t)(b * NN + nn + tid) * 8);
#pragma unroll
            for (int i = 0; i < 5; i++) {
                int e = tid + i * 128;
                int r = e >> 3, cs = (e & 7) * 8;
                cpa16(&v_s[nxt][r][cs], g_vp + (size_t)(b * MR + r) * NN + nn + cs);
            }
            cpa_commit();
            cpa_wait<1>();
        } else {
            cpa_wait<0>();
        }
        __syncthreads();  // current buffer ready; e_s free

        // ---- S = q^T k, fused exp -> e_s (warp: 16 n-rows x 32 m-cols) ----
        unsigned a0, a1;
        ldm_x2(a0, a1, smem_u32(&q_s[cur][nw0 + (lane & 15)][0]));
#pragma unroll
        for (int mt = 0; mt < 4; mt++) {
            float sacc[4] = {0.f, 0.f, 0.f, 0.f};
            mma_k8(sacc, a0, a1, kb[mt]);
            int col = mt * 8 + tc * 2;
            __half2 h01 = __floats2half2_rn(sacc[0] * L2E, sacc[1] * L2E);
            __half2 h23 = __floats2half2_rn(sacc[2] * L2E, sacc[3] * L2E);
            unsigned e01, e23;
            asm volatile("ex2.approx.f16x2 %0, %1;\n" : "=r"(e01) : "r"(*(unsigned*)&h01));
            asm volatile("ex2.approx.f16x2 %0, %1;\n" : "=r"(e23) : "r"(*(unsigned*)&h23));
            *(unsigned*)&e_s[nw0 + g][col]     = e01;
            *(unsigned*)&e_s[nw0 + 8 + g][col] = e23;
        }
        __syncthreads();  // e_s complete

        // ---- O += V'[80 x 64] @ E[64 x 32] : warp owns 8-wide m-strip ----
#pragma unroll
        for (int ks = 0; ks < BN / 16; ks++) {
            unsigned b0, b1;
            ldm_x2_t(b0, b1, smem_u32(&e_s[ks * 16 + (lane & 15)][ms0]));
#pragma unroll
            for (int mt = 0; mt < 5; mt++) {
                unsigned v0, v1, v2, v3;
                ldm_x4(v0, v1, v2, v3,
                       smem_u32(&v_s[cur][mt * 16 + (lane & 15)][ks * 16 + 8 * (lane >> 4)]));
                mma_k16(O[mt], v0, v1, v2, v3, b0, b1);
            }
        }
        __syncthreads();  // protect e_s
    }

    // ---- write fp32 partials: rows 0..63 + denominator row 64 ----
    float* P = g_part + ((size_t)(sp * BB + b) * 65) * NN + m0;
#pragma unroll
    for (int mt = 0; mt < 4; mt++) {
        int col = ms0 + tc * 2;
        int r0 = mt * 16 + g, r1 = r0 + 8;
        P[(size_t)r0 * NN + col]     = O[mt][0];
        P[(size_t)r0 * NN + col + 1] = O[mt][1];
        P[(size_t)r1 * NN + col]     = O[mt][2];
        P[(size_t)r1 * NN + col + 1] = O[mt][3];
    }
    if (g == 0) {   // row 64 = denominator
        int col = ms0 + tc * 2;
        P[(size_t)64 * NN + col]     = O[4][0];
        P[(size_t)64 * NN + col + 1] = O[4][1];
    }
}

// ---------------------------------------------------------------------------
// Combine: out = gamma * (O0+O1)/(d0+d1) + x   (float4 vectorized)
// ---------------------------------------------------------------------------
__global__ __launch_bounds__(256) void combine_kernel(
    const float* __restrict__ x,
    const float* __restrict__ gamma,
    float* __restrict__ out)
{
    const int idx = blockIdx.x * 256 + threadIdx.x;    // 0 .. B*C*N/4-1
    const int e = idx * 4;
    const int b = e >> 18;               // / (64*4096)
    const int c = (e >> 12) & 63;
    const int m = e & (NN - 1);

    const float* P0 = g_part + ((size_t)(0 * BB + b) * 65) * NN;
    const float* P1 = g_part + ((size_t)(1 * BB + b) * 65) * NN;

    float4 n0 = *(const float4*)(P0 + (size_t)c * NN + m);
    float4 n1 = *(const float4*)(P1 + (size_t)c * NN + m);
    float4 d0 = *(const float4*)(P0 + (size_t)64 * NN + m);
    float4 d1 = *(const float4*)(P1 + (size_t)64 * NN + m);
    float4 xv = *(const float4*)(x + (size_t)(b * CC + c) * NN + m);
    const float gam = *gamma;

    float4 o;
    o.x = gam * (n0.x + n1.x) / (d0.x + d1.x) + xv.x;
    o.y = gam * (n0.y + n1.y) / (d0.y + d1.y) + xv.y;
    o.z = gam * (n0.z + n1.z) / (d0.z + d1.z) + xv.z;
    o.w = gam * (n0.w + n1.w) / (d0.w + d1.w) + xv.w;
    *(float4*)(out + (size_t)(b * CC + c) * NN + m) = o;
}

// ---------------------------------------------------------------------------
extern "C" void kernel_launch(void* const* d_in, const int* in_sizes, int n_in,
                              void* d_out, int out_size)
{
    const float* x     = (const float*)d_in[0];
    const float* Wq    = (const float*)d_in[1];
    const float* Wk    = (const float*)d_in[2];
    const float* Wv    = (const float*)d_in[3];
    const float* gamma = (const float*)d_in[4];
    float* out = (float*)d_out;

    proj_kernel<<<(BB * NN) / 128, 128>>>(x, Wq, Wk, Wv);
    attn_kernel<<<dim3(NN / BM, BB, NSPLIT), 128>>>();
    combine_kernel<<<(BB * CC * NN) / (256 * 4), 256>>>(x, gamma, out);
}

// round 5
// speedup vs baseline: 2.4401x; 1.0230x over previous
#include <cuda_runtime.h>
#include <cuda_fp16.h>

// Problem constants
#define BB 4
#define CC 64
#define NN 4096
#define DD 8      // q/k dim = C/8
#define MR 80     // v rows padded: 64 v + 1 ones + 15 zeros (tile M by 16)
#define BM 32     // m-columns per CTA (attn)
#define NSPLIT 2  // split-K over the n (reduction) axis
#define NHALF (NN / NSPLIT)     // 2048
#define BN 64     // n tile
#define NT (NHALF / BN)         // 32 tiles per CTA

#define PC 32     // proj: columns per CTA

// Scratch (allocation-free: __device__ globals)
__device__ __half g_qt[BB * NN * DD];        // [b][n][8]
__device__ __half g_kt[BB * NN * DD];        // [b][m][8]
__device__ __half g_vp[BB * MR * NN];        // [b][r][n]
__device__ float  g_part[NSPLIT * BB * 65 * NN];  // partial O (+denom row 64), 8.5MB

// ---------------------------------------------------------------------------
// Projection kernel v2: out[80, N] = W'[80, 64] @ x[64, N], fp32, smem-tiled.
// Rows 0..7 = q, 8..15 = k, 16..79 = v.  512 CTAs x 128 threads.
// Thread = (4 columns) x (5 rows).  Per c-iter: 1 LDS.128 + 5 LDS + 20 FFMA.
// ---------------------------------------------------------------------------
__global__ __launch_bounds__(128) void proj_kernel(
    const float* __restrict__ x,
    const float* __restrict__ Wq,
    const float* __restrict__ Wk,
    const float* __restrict__ Wv)
{
    __shared__ float xs[64][36];    // 32 cols + pad (stride 144B)  9.2 KB
    __shared__ float wt[64][84];    // [c][row0..79] + pad          21.5 KB

    const int tid = threadIdx.x;
    const int gcol0 = blockIdx.x * PC;          // global column base
    const int b  = gcol0 >> 12;
    const int n0 = gcol0 & (NN - 1);

    // ---- stage weights transposed: wt[c][r] ----
    for (int i = tid; i < 512; i += 128) {      // q rows 0..7
        int j = i >> 6, c = i & 63;
        wt[c][j] = Wq[i];
    }
    for (int i = tid; i < 512; i += 128) {      // k rows 8..15
        int j = i >> 6, c = i & 63;
        wt[c][8 + j] = Wk[i];
    }
    for (int i = tid; i < 4096; i += 128) {     // v rows 16..79
        int o = i >> 6, c = i & 63;
        wt[c][16 + o] = Wv[i];
    }

    // ---- stage x tile [64 rows x 32 cols] (512 float4 loads) ----
    const float* xb = x + (size_t)b * CC * NN + n0;
#pragma unroll
    for (int i = 0; i < 4; i++) {
        int idx = tid + i * 128;                // 0..511
        int row = idx >> 3, seg = idx & 7;      // 8 float4 per row
        *(float4*)&xs[row][seg * 4] = *(const float4*)(xb + (size_t)row * NN + seg * 4);
    }
    __syncthreads();

    // ---- compute: thread = colgroup (4 cols) x rowgroup (5 rows) ----
    const int cg = tid & 7;                     // 0..7  -> cols cg*4..cg*4+3
    const int rg = tid >> 3;                    // 0..15 -> rows rg*5..rg*5+4
    const int r0 = rg * 5;

    float acc[5][4];
#pragma unroll
    for (int i = 0; i < 5; i++)
#pragma unroll
        for (int j = 0; j < 4; j++) acc[i][j] = 0.f;

#pragma unroll 4
    for (int c = 0; c < 64; c++) {
        float4 xv = *(const float4*)&xs[c][cg * 4];
#pragma unroll
        for (int i = 0; i < 5; i++) {
            float w = wt[c][r0 + i];
            acc[i][0] += w * xv.x;
            acc[i][1] += w * xv.y;
            acc[i][2] += w * xv.z;
            acc[i][3] += w * xv.w;
        }
    }

    // ---- store fp16 results ----
    const int nb = n0 + cg * 4;                 // first of 4 columns
#pragma unroll
    for (int i = 0; i < 5; i++) {
        int r = r0 + i;
        __half h[4];
#pragma unroll
        for (int j = 0; j < 4; j++) h[j] = __float2half_rn(acc[i][j]);
        if (r < 8) {
#pragma unroll
            for (int j = 0; j < 4; j++)
                g_qt[(size_t)(b * NN + nb + j) * 8 + r] = h[j];
        } else if (r < 16) {
#pragma unroll
            for (int j = 0; j < 4; j++)
                g_kt[(size_t)(b * NN + nb + j) * 8 + (r - 8)] = h[j];
        } else {
            *(uint2*)(g_vp + (size_t)b * MR * NN + (size_t)(r - 16) * NN + nb) = *(uint2*)h;
        }
    }

    // ---- pad rows of g_vp: row 64 = ones (rg 0), rows 65..79 = zeros (rg 1..15) ----
    {
        int pr = 64 + rg;                       // each rowgroup owns one pad row
        __half pv = (rg == 0) ? __float2half_rn(1.0f) : __ushort_as_half(0);
        __half h[4] = {pv, pv, pv, pv};
        *(uint2*)(g_vp + (size_t)b * MR * NN + (size_t)pr * NN + nb) = *(uint2*)h;
    }
}

// ---------------------------------------------------------------------------
// helpers
// ---------------------------------------------------------------------------
__device__ __forceinline__ unsigned smem_u32(const void* p) {
    return (unsigned)__cvta_generic_to_shared(p);
}
__device__ __forceinline__ void cpa16(void* dst, const void* src) {
    asm volatile("cp.async.cg.shared.global [%0], [%1], 16;\n"
                 :: "r"(smem_u32(dst)), "l"(src));
}
__device__ __forceinline__ void cpa_commit() {
    asm volatile("cp.async.commit_group;\n");
}
template <int N>
__device__ __forceinline__ void cpa_wait() {
    asm volatile("cp.async.wait_group %0;\n" :: "n"(N));
}
__device__ __forceinline__ void ldm_x2(unsigned& r0, unsigned& r1, unsigned addr) {
    asm volatile("ldmatrix.sync.aligned.m8n8.x2.shared.b16 {%0,%1}, [%2];\n"
                 : "=r"(r0), "=r"(r1) : "r"(addr));
}
__device__ __forceinline__ void ldm_x2_t(unsigned& r0, unsigned& r1, unsigned addr) {
    asm volatile("ldmatrix.sync.aligned.m8n8.x2.trans.shared.b16 {%0,%1}, [%2];\n"
                 : "=r"(r0), "=r"(r1) : "r"(addr));
}
__device__ __forceinline__ void ldm_x4(unsigned& r0, unsigned& r1, unsigned& r2, unsigned& r3, unsigned addr) {
    asm volatile("ldmatrix.sync.aligned.m8n8.x4.shared.b16 {%0,%1,%2,%3}, [%4];\n"
                 : "=r"(r0), "=r"(r1), "=r"(r2), "=r"(r3) : "r"(addr));
}
__device__ __forceinline__ void mma_k8(float* c, unsigned a0, unsigned a1, unsigned b0) {
    asm volatile(
        "mma.sync.aligned.m16n8k8.row.col.f32.f16.f16.f32 "
        "{%0,%1,%2,%3}, {%4,%5}, {%6}, {%0,%1,%2,%3};\n"
        : "+f"(c[0]), "+f"(c[1]), "+f"(c[2]), "+f"(c[3])
        : "r"(a0), "r"(a1), "r"(b0));
}
__device__ __forceinline__ void mma_k16(float* c, unsigned a0, unsigned a1, unsigned a2, unsigned a3,
                                        unsigned b0, unsigned b1) {
    asm volatile(
        "mma.sync.aligned.m16n8k16.row.col.f32.f16.f16.f32 "
        "{%0,%1,%2,%3}, {%4,%5,%6,%7}, {%8,%9}, {%0,%1,%2,%3};\n"
        : "+f"(c[0]), "+f"(c[1]), "+f"(c[2]), "+f"(c[3])
        : "r"(a0), "r"(a1), "r"(a2), "r"(a3), "r"(b0), "r"(b1));
}

// ---------------------------------------------------------------------------
// Attention main: CTA = (m-strip of 32, batch, n-half). 4 warps, 1024 CTAs.
// Writes fp32 partial O (rows 0..63) + denominator (row 64) to g_part.
// ---------------------------------------------------------------------------
__global__ __launch_bounds__(128, 7) void attn_kernel()
{
    __shared__ __half k_s[BM][8];            // 0.5 KB
    __shared__ __half q_s[2][BN][8];         // 2 KB
    __shared__ __half v_s[2][MR][72];        // 22.5 KB (stride 144B: conflict-free)
    __shared__ __half e_s[BN][40];           // 5 KB   (stride 80B: 5r%8 conflict-free)

    const int b  = blockIdx.y;
    const int m0 = blockIdx.x * BM;
    const int sp = blockIdx.z;
    const int s0 = sp * NHALF;
    const int tid = threadIdx.x;
    const int w = tid >> 5, lane = tid & 31, g = lane >> 2, tc = lane & 3;

    // ---- k tile: this CTA's 32 m-columns ----
    if (tid < BM)
        *(uint4*)&k_s[tid][0] = *(const uint4*)(g_kt + (size_t)(b * NN + m0 + tid) * 8);

    // ---- prefetch tile 0 ----
    {
        if (tid < BN)
            cpa16(&q_s[0][tid][0], g_qt + (size_t)(b * NN + s0 + tid) * 8);
#pragma unroll
        for (int i = 0; i < 5; i++) {
            int e = tid + i * 128;                  // 0..639
            int r = e >> 3, cs = (e & 7) * 8;
            cpa16(&v_s[0][r][cs], g_vp + (size_t)(b * MR + r) * NN + s0 + cs);
        }
        cpa_commit();
    }
    __syncthreads();   // k_s ready

    // k fragments: 32 m-cols = 4 n8-tiles (resident whole kernel)
    unsigned kb[4];
    ldm_x4(kb[0], kb[1], kb[2], kb[3], smem_u32(&k_s[lane][0]));

    // PV accumulators: warp owns m-cols [w*8, w*8+8), all 80 rows
    float O[5][4];
#pragma unroll
    for (int mt = 0; mt < 5; mt++)
#pragma unroll
        for (int r = 0; r < 4; r++) O[mt][r] = 0.f;

    const int nw0 = w * 16;      // S-phase: warp's 16 n-rows
    const int ms0 = w * 8;       // PV-phase: warp's 8 m-cols
    const float L2E = 1.44269504f;

    for (int it = 0; it < NT; it++) {
        const int cur = it & 1;

        // ---- prefetch next tile ----
        if (it + 1 < NT) {
            const int nn = s0 + (it + 1) * BN;
            const int nxt = cur ^ 1;
            if (tid < BN)
                cpa16(&q_s[nxt][tid][0], g_qt + (size_t)(b * NN + nn + tid) * 8);
#pragma unroll
            for (int i = 0; i < 5; i++) {
                int e = tid + i * 128;
                int r = e >> 3, cs = (e & 7) * 8;
                cpa16(&v_s[nxt][r][cs], g_vp + (size_t)(b * MR + r) * NN + nn + cs);
            }
            cpa_commit();
            cpa_wait<1>();
        } else {
            cpa_wait<0>();
        }
        __syncthreads();  // current buffer ready; e_s free

        // ---- S = q^T k, fused exp -> e_s (warp: 16 n-rows x 32 m-cols) ----
        unsigned a0, a1;
        ldm_x2(a0, a1, smem_u32(&q_s[cur][nw0 + (lane & 15)][0]));
#pragma unroll
        for (int mt = 0; mt < 4; mt++) {
            float sacc[4] = {0.f, 0.f, 0.f, 0.f};
            mma_k8(sacc, a0, a1, kb[mt]);
            int col = mt * 8 + tc * 2;
            __half2 h01 = __floats2half2_rn(sacc[0] * L2E, sacc[1] * L2E);
            __half2 h23 = __floats2half2_rn(sacc[2] * L2E, sacc[3] * L2E);
            unsigned e01, e23;
            asm volatile("ex2.approx.f16x2 %0, %1;\n" : "=r"(e01) : "r"(*(unsigned*)&h01));
            asm volatile("ex2.approx.f16x2 %0, %1;\n" : "=r"(e23) : "r"(*(unsigned*)&h23));
            *(unsigned*)&e_s[nw0 + g][col]     = e01;
            *(unsigned*)&e_s[nw0 + 8 + g][col] = e23;
        }
        __syncthreads();  // e_s complete

        // ---- O += V'[80 x 64] @ E[64 x 32] : warp owns 8-wide m-strip ----
#pragma unroll
        for (int ks = 0; ks < BN / 16; ks++) {
            unsigned b0, b1;
            ldm_x2_t(b0, b1, smem_u32(&e_s[ks * 16 + (lane & 15)][ms0]));
#pragma unroll
            for (int mt = 0; mt < 5; mt++) {
                unsigned v0, v1, v2, v3;
                ldm_x4(v0, v1, v2, v3,
                       smem_u32(&v_s[cur][mt * 16 + (lane & 15)][ks * 16 + 8 * (lane >> 4)]));
                mma_k16(O[mt], v0, v1, v2, v3, b0, b1);
            }
        }
        __syncthreads();  // protect e_s
    }

    // ---- write fp32 partials: rows 0..63 + denominator row 64 ----
    float* P = g_part + ((size_t)(sp * BB + b) * 65) * NN + m0;
#pragma unroll
    for (int mt = 0; mt < 4; mt++) {
        int col = ms0 + tc * 2;
        int r0 = mt * 16 + g, r1 = r0 + 8;
        P[(size_t)r0 * NN + col]     = O[mt][0];
        P[(size_t)r0 * NN + col + 1] = O[mt][1];
        P[(size_t)r1 * NN + col]     = O[mt][2];
        P[(size_t)r1 * NN + col + 1] = O[mt][3];
    }
    if (g == 0) {   // row 64 = denominator
        int col = ms0 + tc * 2;
        P[(size_t)64 * NN + col]     = O[4][0];
        P[(size_t)64 * NN + col + 1] = O[4][1];
    }
}

// ---------------------------------------------------------------------------
// Combine: out = gamma * (O0+O1)/(d0+d1) + x   (float4 vectorized)
// ---------------------------------------------------------------------------
__global__ __launch_bounds__(256) void combine_kernel(
    const float* __restrict__ x,
    const float* __restrict__ gamma,
    float* __restrict__ out)
{
    const int idx = blockIdx.x * 256 + threadIdx.x;    // 0 .. B*C*N/4-1
    const int e = idx * 4;
    const int b = e >> 18;               // / (64*4096)
    const int c = (e >> 12) & 63;
    const int m = e & (NN - 1);

    const float* P0 = g_part + ((size_t)(0 * BB + b) * 65) * NN;
    const float* P1 = g_part + ((size_t)(1 * BB + b) * 65) * NN;

    float4 n0 = *(const float4*)(P0 + (size_t)c * NN + m);
    float4 n1 = *(const float4*)(P1 + (size_t)c * NN + m);
    float4 d0 = *(const float4*)(P0 + (size_t)64 * NN + m);
    float4 d1 = *(const float4*)(P1 + (size_t)64 * NN + m);
    float4 xv = *(const float4*)(x + (size_t)(b * CC + c) * NN + m);
    const float gam = *gamma;

    float4 o;
    o.x = gam * (n0.x + n1.x) / (d0.x + d1.x) + xv.x;
    o.y = gam * (n0.y + n1.y) / (d0.y + d1.y) + xv.y;
    o.z = gam * (n0.z + n1.z) / (d0.z + d1.z) + xv.z;
    o.w = gam * (n0.w + n1.w) / (d0.w + d1.w) + xv.w;
    *(float4*)(out + (size_t)(b * CC + c) * NN + m) = o;
}

// ---------------------------------------------------------------------------
extern "C" void kernel_launch(void* const* d_in, const int* in_sizes, int n_in,
                              void* d_out, int out_size)
{
    const float* x     = (const float*)d_in[0];
    const float* Wq    = (const float*)d_in[1];
    const float* Wk    = (const float*)d_in[2];
    const float* Wv    = (const float*)d_in[3];
    const float* gamma = (const float*)d_in[4];
    float* out = (float*)d_out;

    proj_kernel<<<(BB * NN) / PC, 128>>>(x, Wq, Wk, Wv);
    attn_kernel<<<dim3(NN / BM, BB, NSPLIT), 128>>>();
    combine_kernel<<<(BB * CC * NN) / (256 * 4), 256>>>(x, gamma, out);
}

// round 7
// speedup vs baseline: 2.5707x; 1.0535x over previous
#include <cuda_runtime.h>
#include <cuda_fp16.h>

// Problem constants
#define BB 4
#define CC 64
#define NN 4096
#define DD 8      // q/k dim = C/8
#define MR 80     // v rows padded: 64 v + 1 ones + 15 zeros
#define BM 32     // m-columns per CTA (attn)
#define NSPLIT 2  // split-K over n
#define NHALF (NN / NSPLIT)     // 2048
#define BN 64     // n tile
#define NT (NHALF / BN)         // 32 tiles per CTA

#define PC 16     // proj: columns per CTA

// Scratch (allocation-free: __device__ globals)
__device__ __half g_qt[BB * NN * DD];        // [b][n][8]
__device__ __half g_kt[BB * NN * DD];        // [b][m][8]
__device__ __half g_vp[BB * NN * MR];        // [b][n][r]  TRANSPOSED: r<64 v, r=64 ones, 65..79 zero
__device__ float  g_part[NSPLIT * BB * 65 * NN];  // partial O (+denom row 64)

// ---------------------------------------------------------------------------
// Projection: out[80, N] = W'[80,64] @ x[64,N].  1024 CTAs x 128 thr.
// q -> g_qt[n][8], k -> g_kt[n][8], v -> g_vp[n][80] (transposed via smem).
// ---------------------------------------------------------------------------
__global__ __launch_bounds__(128) void proj_kernel(
    const float* __restrict__ x,
    const float* __restrict__ Wq,
    const float* __restrict__ Wk,
    const float* __restrict__ Wv)
{
    __shared__ float  xs[64][20];    // 16 cols + pad (stride 80B)   5.1 KB
    __shared__ float  wt[64][84];    // [c][row 0..79] + pad         21.5 KB
    __shared__ __half vs[PC][88];    // v-transpose staging          2.8 KB

    const int tid = threadIdx.x;
    const int gcol0 = blockIdx.x * PC;
    const int b  = gcol0 >> 12;
    const int n0 = gcol0 & (NN - 1);

    // ---- stage weights transposed: wt[c][r] ----
    for (int i = tid; i < 512; i += 128) {      // q rows 0..7
        int j = i >> 6, c = i & 63;
        wt[c][j] = Wq[i];
    }
    for (int i = tid; i < 512; i += 128) {      // k rows 8..15
        int j = i >> 6, c = i & 63;
        wt[c][8 + j] = Wk[i];
    }
    for (int i = tid; i < 4096; i += 128) {     // v rows 16..79
        int o = i >> 6, c = i & 63;
        wt[c][16 + o] = Wv[i];
    }

    // ---- stage x tile [64 x 16] (256 float4) ----
    const float* xb = x + (size_t)b * CC * NN + n0;
#pragma unroll
    for (int i = 0; i < 2; i++) {
        int idx = tid + i * 128;                // 0..255
        int row = idx >> 2, seg = idx & 3;
        *(float4*)&xs[row][seg * 4] = *(const float4*)(xb + (size_t)row * NN + seg * 4);
    }
    __syncthreads();

    // ---- compute: thread = (2 cols) x (5 rows) ----
    const int cg = tid & 7;                     // cols cg*2, cg*2+1
    const int rg = tid >> 3;                    // rows rg*5 .. rg*5+4
    const int r0 = rg * 5;

    float acc[5][2];
#pragma unroll
    for (int i = 0; i < 5; i++) { acc[i][0] = 0.f; acc[i][1] = 0.f; }

#pragma unroll 8
    for (int c = 0; c < 64; c++) {
        float2 xv = *(const float2*)&xs[c][cg * 2];
#pragma unroll
        for (int i = 0; i < 5; i++) {
            float w = wt[c][r0 + i];
            acc[i][0] += w * xv.x;
            acc[i][1] += w * xv.y;
        }
    }

    // ---- scatter results: q/k direct, v into smem transpose buffer ----
    const int nb = n0 + cg * 2;
#pragma unroll
    for (int i = 0; i < 5; i++) {
        int r = r0 + i;
        __half h0 = __float2half_rn(acc[i][0]);
        __half h1 = __float2half_rn(acc[i][1]);
        if (r < 8) {
            g_qt[(size_t)(b * NN + nb) * 8 + r]     = h0;
            g_qt[(size_t)(b * NN + nb + 1) * 8 + r] = h1;
        } else if (r < 16) {
            g_kt[(size_t)(b * NN + nb) * 8 + (r - 8)]     = h0;
            g_kt[(size_t)(b * NN + nb + 1) * 8 + (r - 8)] = h1;
        } else {
            vs[cg * 2][r - 16]     = h0;
            vs[cg * 2 + 1][r - 16] = h1;
        }
    }
    if (tid < PC) {                              // pad rows: ones + zeros
        vs[tid][64] = __float2half_rn(1.0f);
#pragma unroll
        for (int r = 65; r < MR; r++) vs[tid][r] = __ushort_as_half(0);
    }
    __syncthreads();

    // ---- cooperative v store: 16 n-cols x 10 uint4 ----
    for (int i = tid; i < PC * 10; i += 128) {
        int nl = i / 10, seg = i % 10;
        *(uint4*)(g_vp + ((size_t)(b * NN + n0 + nl)) * MR + seg * 8) = *(uint4*)&vs[nl][seg * 8];
    }
}

// ---------------------------------------------------------------------------
// helpers
// ---------------------------------------------------------------------------
__device__ __forceinline__ unsigned smem_u32(const void* p) {
    return (unsigned)__cvta_generic_to_shared(p);
}
__device__ __forceinline__ void cpa16(void* dst, const void* src) {
    asm volatile("cp.async.cg.shared.global [%0], [%1], 16;\n"
                 :: "r"(smem_u32(dst)), "l"(src));
}
__device__ __forceinline__ void cpa_commit() {
    asm volatile("cp.async.commit_group;\n");
}
template <int N>
__device__ __forceinline__ void cpa_wait() {
    asm volatile("cp.async.wait_group %0;\n" :: "n"(N));
}
__device__ __forceinline__ void ldm_x2(unsigned& r0, unsigned& r1, unsigned addr) {
    asm volatile("ldmatrix.sync.aligned.m8n8.x2.shared.b16 {%0,%1}, [%2];\n"
                 : "=r"(r0), "=r"(r1) : "r"(addr));
}
__device__ __forceinline__ void ldm_x2_t(unsigned& r0, unsigned& r1, unsigned addr) {
    asm volatile("ldmatrix.sync.aligned.m8n8.x2.trans.shared.b16 {%0,%1}, [%2];\n"
                 : "=r"(r0), "=r"(r1) : "r"(addr));
}
__device__ __forceinline__ void ldm_x4(unsigned& r0, unsigned& r1, unsigned& r2, unsigned& r3, unsigned addr) {
    asm volatile("ldmatrix.sync.aligned.m8n8.x4.shared.b16 {%0,%1,%2,%3}, [%4];\n"
                 : "=r"(r0), "=r"(r1), "=r"(r2), "=r"(r3) : "r"(addr));
}
__device__ __forceinline__ void ldm_x4_t(unsigned& r0, unsigned& r1, unsigned& r2, unsigned& r3, unsigned addr) {
    asm volatile("ldmatrix.sync.aligned.m8n8.x4.trans.shared.b16 {%0,%1,%2,%3}, [%4];\n"
                 : "=r"(r0), "=r"(r1), "=r"(r2), "=r"(r3) : "r"(addr));
}
__device__ __forceinline__ void mma_k8(float* c, unsigned a0, unsigned a1, unsigned b0) {
    asm volatile(
        "mma.sync.aligned.m16n8k8.row.col.f32.f16.f16.f32 "
        "{%0,%1,%2,%3}, {%4,%5}, {%6}, {%0,%1,%2,%3};\n"
        : "+f"(c[0]), "+f"(c[1]), "+f"(c[2]), "+f"(c[3])
        : "r"(a0), "r"(a1), "r"(b0));
}
__device__ __forceinline__ void mma_k16(float* c, unsigned a0, unsigned a1, unsigned a2, unsigned a3,
                                        unsigned b0, unsigned b1) {
    asm volatile(
        "mma.sync.aligned.m16n8k16.row.col.f32.f16.f16.f32 "
        "{%0,%1,%2,%3}, {%4,%5,%6,%7}, {%8,%9}, {%0,%1,%2,%3};\n"
        : "+f"(c[0]), "+f"(c[1]), "+f"(c[2]), "+f"(c[3])
        : "r"(a0), "r"(a1), "r"(a2), "r"(a3), "r"(b0), "r"(b1));
}

// ---------------------------------------------------------------------------
// Attention main: CTA = (32 m-cols, batch, n-half). 4 warps, 1024 CTAs.
// S^T = k q^T via m16n8k8 (A=k, B=q); exp in registers; S^T C-fragments ARE
// the A-fragments of the PV m16n8k16 (FA2 identity) -> no E smem roundtrip.
// O^T[m, r] = E^T V'^T; V' staged n-major from g_vp.
// Warp = (m-tile w&1) x (r-half w>>1). Row 64 of V' = ones -> denominator.
// ---------------------------------------------------------------------------
__global__ __launch_bounds__(128, 6) void attn_kernel()
{
    __shared__ __half k_s[BM][8];            // 0.5 KB
    __shared__ __half q_s[2][BN][8];         // 2 KB
    __shared__ __half v_s[2][BN][88];        // 22.5 KB (stride 176B: conflict-free)

    const int b  = blockIdx.y;
    const int m0 = blockIdx.x * BM;
    const int sp = blockIdx.z;
    const int s0 = sp * NHALF;
    const int tid = threadIdx.x;
    const int w = tid >> 5, lane = tid & 31, g = lane >> 2, tc = lane & 3;
    const int mt_ = w & 1;       // m-tile: cols mt_*16 .. +15
    const int rh  = w >> 1;      // r-half: rows rh*40 .. +39

    // ---- k tile ----
    if (tid < BM)
        *(uint4*)&k_s[tid][0] = *(const uint4*)(g_kt + (size_t)(b * NN + m0 + tid) * 8);

    // ---- prefetch tile 0 ----
    {
        if (tid < BN)
            cpa16(&q_s[0][tid][0], g_qt + (size_t)(b * NN + s0 + tid) * 8);
#pragma unroll
        for (int i = 0; i < 5; i++) {
            int e = tid + i * 128;                  // 0..639
            int nl = e / 10, seg = e % 10;
            cpa16(&v_s[0][nl][seg * 8], g_vp + (size_t)(b * NN + s0 + nl) * MR + seg * 8);
        }
        cpa_commit();
    }
    __syncthreads();   // k_s ready

    // A fragments for S^T: k rows m (resident whole kernel)
    unsigned ka0, ka1;
    ldm_x2(ka0, ka1, smem_u32(&k_s[mt_ * 16 + (lane & 15)][0]));

    // O^T accumulators: m16 x (5 r8-tiles)
    float O[5][4];
#pragma unroll
    for (int rt = 0; rt < 5; rt++)
#pragma unroll
        for (int r = 0; r < 4; r++) O[rt][r] = 0.f;

    const float L2E = 1.44269504f;

    for (int it = 0; it < NT; it++) {
        const int cur = it & 1;

        // ---- prefetch next tile ----
        if (it + 1 < NT) {
            const int nn = s0 + (it + 1) * BN;
            const int nxt = cur ^ 1;
            if (tid < BN)
                cpa16(&q_s[nxt][tid][0], g_qt + (size_t)(b * NN + nn + tid) * 8);
#pragma unroll
            for (int i = 0; i < 5; i++) {
                int e = tid + i * 128;
                int nl = e / 10, seg = e % 10;
                cpa16(&v_s[nxt][nl][seg * 8], g_vp + (size_t)(b * NN + nn + nl) * MR + seg * 8);
            }
            cpa_commit();
            cpa_wait<1>();
        } else {
            cpa_wait<0>();
        }
        __syncthreads();  // current buffer ready

        // ---- q B-fragments: 8 n8-tiles ----
        unsigned qb[8];
        ldm_x4(qb[0], qb[1], qb[2], qb[3], smem_u32(&q_s[cur][lane][0]));
        ldm_x4(qb[4], qb[5], qb[6], qb[7], smem_u32(&q_s[cur][32 + lane][0]));

        // ---- S^T + exp -> PV A-fragments (registers only) ----
        unsigned ea[4][4];
#pragma unroll
        for (int nt = 0; nt < 8; nt++) {
            float s[4] = {0.f, 0.f, 0.f, 0.f};
            mma_k8(s, ka0, ka1, qb[nt]);
            __half2 h01 = __floats2half2_rn(s[0] * L2E, s[1] * L2E);
            __half2 h23 = __floats2half2_rn(s[2] * L2E, s[3] * L2E);
            unsigned e01, e23;
            asm volatile("ex2.approx.f16x2 %0, %1;\n" : "=r"(e01) : "r"(*(unsigned*)&h01));
            asm volatile("ex2.approx.f16x2 %0, %1;\n" : "=r"(e23) : "r"(*(unsigned*)&h23));
            ea[nt >> 1][(nt & 1) * 2]     = e01;   // a0 / a2
            ea[nt >> 1][(nt & 1) * 2 + 1] = e23;   // a1 / a3
        }

        // ---- O^T += E^T[m16, n64] @ V'^T[n64, r40] ----
#pragma unroll
        for (int ks = 0; ks < 4; ks++) {
            unsigned vb[10];
            ldm_x4_t(vb[0], vb[1], vb[2], vb[3],
                     smem_u32(&v_s[cur][ks * 16 + (lane & 15)][rh * 40 + 8 * (lane >> 4)]));
            ldm_x4_t(vb[4], vb[5], vb[6], vb[7],
                     smem_u32(&v_s[cur][ks * 16 + (lane & 15)][rh * 40 + 16 + 8 * (lane >> 4)]));
            ldm_x2_t(vb[8], vb[9],
                     smem_u32(&v_s[cur][ks * 16 + (lane & 15)][rh * 40 + 32]));
#pragma unroll
            for (int rt = 0; rt < 5; rt++)
                mma_k16(O[rt], ea[ks][0], ea[ks][1], ea[ks][2], ea[ks][3],
                        vb[2 * rt], vb[2 * rt + 1]);
        }
        __syncthreads();  // all reads done before next prefetch overwrites
    }

    // ---- write fp32 partials (transposed): P[r][m].  r = rh*40+rt*8+tc*2 ----
    float* P = g_part + ((size_t)(sp * BB + b) * 65) * NN + m0;
    const int m = mt_ * 16 + g;
#pragma unroll
    for (int rt = 0; rt < 5; rt++) {
        int r = rh * 40 + rt * 8 + tc * 2;
        if (r < 64) {
            P[(size_t)r * NN + m]           = O[rt][0];
            P[(size_t)(r + 1) * NN + m]     = O[rt][1];
            P[(size_t)r * NN + m + 8]       = O[rt][2];
            P[(size_t)(r + 1) * NN + m + 8] = O[rt][3];
        } else if (r == 64) {   // denominator row
            P[(size_t)64 * NN + m]     = O[rt][0];
            P[(size_t)64 * NN + m + 8] = O[rt][2];
        }
    }
}

// ---------------------------------------------------------------------------
// Combine: out = gamma * (O0+O1)/(d0+d1) + x
// ---------------------------------------------------------------------------
__global__ __launch_bounds__(256) void combine_kernel(
    const float* __restrict__ x,
    const float* __restrict__ gamma,
    float* __restrict__ out)
{
    const int idx = blockIdx.x * 256 + threadIdx.x;
    const int e = idx * 4;
    const int b = e >> 18;
    const int c = (e >> 12) & 63;
    const int m = e & (NN - 1);

    const float* P0 = g_part + ((size_t)(0 * BB + b) * 65) * NN;
    const float* P1 = g_part + ((size_t)(1 * BB + b) * 65) * NN;

    float4 n0 = *(const float4*)(P0 + (size_t)c * NN + m);
    float4 n1 = *(const float4*)(P1 + (size_t)c * NN + m);
    float4 d0 = *(const float4*)(P0 + (size_t)64 * NN + m);
    float4 d1 = *(const float4*)(P1 + (size_t)64 * NN + m);
    float4 xv = *(const float4*)(x + (size_t)(b * CC + c) * NN + m);
    const float gam = *gamma;

    float4 o;
    o.x = gam * (n0.x + n1.x) / (d0.x + d1.x) + xv.x;
    o.y = gam * (n0.y + n1.y) / (d0.y + d1.y) + xv.y;
    o.z = gam * (n0.z + n1.z) / (d0.z + d1.z) + xv.z;
    o.w = gam * (n0.w + n1.w) / (d0.w + d1.w) + xv.w;
    *(float4*)(out + (size_t)(b * CC + c) * NN + m) = o;
}

// ---------------------------------------------------------------------------
extern "C" void kernel_launch(void* const* d_in, const int* in_sizes, int n_in,
                              void* d_out, int out_size)
{
    const float* x     = (const float*)d_in[0];
    const float* Wq    = (const float*)d_in[1];
    const float* Wk    = (const float*)d_in[2];
    const float* Wv    = (const float*)d_in[3];
    const float* gamma = (const float*)d_in[4];
    float* out = (float*)d_out;

    proj_kernel<<<(BB * NN) / PC, 128>>>(x, Wq, Wk, Wv);
    attn_kernel<<<dim3(NN / BM, BB, NSPLIT), 128>>>();
    combine_kernel<<<(BB * CC * NN) / (256 * 4), 256>>>(x, gamma, out);
}

// round 8
// speedup vs baseline: 3.0760x; 1.1966x over previous
#include <cuda_runtime.h>
#include <cuda_fp16.h>

// Problem constants
#define BB 4
#define CC 64
#define NN 4096
#define DD 8      // q/k dim = C/8
#define MR 80     // v rows padded: 64 v + 1 ones + 15 zeros
#define BM 32     // m-columns per CTA (attn)
#define NSPLIT 2  // split-K over n
#define NHALF (NN / NSPLIT)     // 2048
#define BN 64     // n tile
#define NT (NHALF / BN)         // 32 tiles per CTA

// Scratch (allocation-free: __device__ globals)
__device__ __half g_qt[BB * NN * DD];        // [b][n][8]
__device__ __half g_kt[BB * NN * DD];        // [b][m][8]
__device__ __half g_vp[BB * NN * MR];        // [b][n][r]: r<64 v, r=64 ones, 65..79 zero
__device__ float  g_part[NSPLIT * BB * 65 * NN];  // partial O (+denom row 64)

// ---------------------------------------------------------------------------
// helpers
// ---------------------------------------------------------------------------
__device__ __forceinline__ unsigned smem_u32(const void* p) {
    return (unsigned)__cvta_generic_to_shared(p);
}
__device__ __forceinline__ void cpa16(void* dst, const void* src) {
    asm volatile("cp.async.cg.shared.global [%0], [%1], 16;\n"
                 :: "r"(smem_u32(dst)), "l"(src));
}
__device__ __forceinline__ void cpa_commit() {
    asm volatile("cp.async.commit_group;\n");
}
template <int N>
__device__ __forceinline__ void cpa_wait() {
    asm volatile("cp.async.wait_group %0;\n" :: "n"(N));
}
__device__ __forceinline__ void ldm_x2(unsigned& r0, unsigned& r1, unsigned addr) {
    asm volatile("ldmatrix.sync.aligned.m8n8.x2.shared.b16 {%0,%1}, [%2];\n"
                 : "=r"(r0), "=r"(r1) : "r"(addr));
}
__device__ __forceinline__ void ldm_x2_t(unsigned& r0, unsigned& r1, unsigned addr) {
    asm volatile("ldmatrix.sync.aligned.m8n8.x2.trans.shared.b16 {%0,%1}, [%2];\n"
                 : "=r"(r0), "=r"(r1) : "r"(addr));
}
__device__ __forceinline__ void ldm_x4(unsigned& r0, unsigned& r1, unsigned& r2, unsigned& r3, unsigned addr) {
    asm volatile("ldmatrix.sync.aligned.m8n8.x4.shared.b16 {%0,%1,%2,%3}, [%4];\n"
                 : "=r"(r0), "=r"(r1), "=r"(r2), "=r"(r3) : "r"(addr));
}
__device__ __forceinline__ void ldm_x4_t(unsigned& r0, unsigned& r1, unsigned& r2, unsigned& r3, unsigned addr) {
    asm volatile("ldmatrix.sync.aligned.m8n8.x4.trans.shared.b16 {%0,%1,%2,%3}, [%4];\n"
                 : "=r"(r0), "=r"(r1), "=r"(r2), "=r"(r3) : "r"(addr));
}
__device__ __forceinline__ void mma_k8(float* c, unsigned a0, unsigned a1, unsigned b0) {
    asm volatile(
        "mma.sync.aligned.m16n8k8.row.col.f32.f16.f16.f32 "
        "{%0,%1,%2,%3}, {%4,%5}, {%6}, {%0,%1,%2,%3};\n"
        : "+f"(c[0]), "+f"(c[1]), "+f"(c[2]), "+f"(c[3])
        : "r"(a0), "r"(a1), "r"(b0));
}
__device__ __forceinline__ void mma_k16(float* c, unsigned a0, unsigned a1, unsigned a2, unsigned a3,
                                        unsigned b0, unsigned b1) {
    asm volatile(
        "mma.sync.aligned.m16n8k16.row.col.f32.f16.f16.f32 "
        "{%0,%1,%2,%3}, {%4,%5,%6,%7}, {%8,%9}, {%0,%1,%2,%3};\n"
        : "+f"(c[0]), "+f"(c[1]), "+f"(c[2]), "+f"(c[3])
        : "r"(a0), "r"(a1), "r"(a2), "r"(a3), "r"(b0), "r"(b1));
}

// ---------------------------------------------------------------------------
// Projection v3 (tensor cores): out[80, N] = W'[80,64] @ x[64,N], fp16 in,
// fp32 accum.  CTA = 64 n-cols, 4 warps (warp = 16-col strip), 256 CTAs.
// A-frags: ldm_x4 on row-major w_s (proven pattern); B: ldm_x4_t on x_s.
// ---------------------------------------------------------------------------
__global__ __launch_bounds__(128) void proj_kernel(
    const float* __restrict__ x,
    const float* __restrict__ Wq,
    const float* __restrict__ Wk,
    const float* __restrict__ Wv)
{
    __shared__ __half w_s[80][72];   // 11.5 KB (stride 144B: conflict-free)
    __shared__ __half x_s[64][72];   // 9 KB
    __shared__ __half o_s[80][72];   // 11.5 KB

    const int tid = threadIdx.x;
    const int lane = tid & 31, w = tid >> 5;
    const int g = lane >> 2, tc = lane & 3;
    const int gcol0 = blockIdx.x * 64;
    const int b  = gcol0 >> 12;
    const int n0 = gcol0 & (NN - 1);

    // ---- stage weights fp32->fp16: rows 0..7 q, 8..15 k, 16..79 v ----
    for (int i = tid; i < 1280; i += 128) {       // 1280 float4
        int r = i >> 4, s = i & 15;
        const float* src;
        if (r < 8)       src = Wq + r * 64 + s * 4;
        else if (r < 16) src = Wk + (r - 8) * 64 + s * 4;
        else             src = Wv + (r - 16) * 64 + s * 4;
        float4 v = *(const float4*)src;
        __half h[4] = {__float2half_rn(v.x), __float2half_rn(v.y),
                       __float2half_rn(v.z), __float2half_rn(v.w)};
        *(uint2*)&w_s[r][s * 4] = *(uint2*)h;
    }

    // ---- stage x tile [64 x 64] fp32->fp16 ----
    const float* xb = x + (size_t)b * CC * NN + n0;
    for (int i = tid; i < 1024; i += 128) {       // 1024 float4
        int row = i >> 4, s = i & 15;
        float4 v = *(const float4*)(xb + (size_t)row * NN + s * 4);
        __half h[4] = {__float2half_rn(v.x), __float2half_rn(v.y),
                       __float2half_rn(v.z), __float2half_rn(v.w)};
        *(uint2*)&x_s[row][s * 4] = *(uint2*)h;
    }
    __syncthreads();

    // ---- MMA: warp w owns n-strip [w*16, w*16+16) ----
    const int nb = w * 16;
    float acc[5][2][4];
#pragma unroll
    for (int m = 0; m < 5; m++)
#pragma unroll
        for (int nt = 0; nt < 2; nt++)
#pragma unroll
            for (int r = 0; r < 4; r++) acc[m][nt][r] = 0.f;

#pragma unroll
    for (int k = 0; k < 4; k++) {
        unsigned b0, b1, b2, b3;
        ldm_x4_t(b0, b1, b2, b3,
                 smem_u32(&x_s[k * 16 + (lane & 15)][nb + 8 * (lane >> 4)]));
#pragma unroll
        for (int m = 0; m < 5; m++) {
            unsigned a0, a1, a2, a3;
            ldm_x4(a0, a1, a2, a3,
                   smem_u32(&w_s[m * 16 + (lane & 15)][k * 16 + 8 * (lane >> 4)]));
            mma_k16(acc[m][0], a0, a1, a2, a3, b0, b1);
            mma_k16(acc[m][1], a0, a1, a2, a3, b2, b3);
        }
    }

    // ---- C fragments -> o_s (fp16) ----
#pragma unroll
    for (int m = 0; m < 5; m++)
#pragma unroll
        for (int nt = 0; nt < 2; nt++) {
            int row = m * 16 + g, col = nb + nt * 8 + tc * 2;
            o_s[row][col]         = __float2half_rn(acc[m][nt][0]);
            o_s[row][col + 1]     = __float2half_rn(acc[m][nt][1]);
            o_s[row + 8][col]     = __float2half_rn(acc[m][nt][2]);
            o_s[row + 8][col + 1] = __float2half_rn(acc[m][nt][3]);
        }
    __syncthreads();

    // ---- transpose-scatter: q/k (one uint4 per n-col each) ----
    {
        int n = tid & 63;
        __half h[8];
        if (tid < 64) {
#pragma unroll
            for (int r = 0; r < 8; r++) h[r] = o_s[r][n];
            *(uint4*)(g_qt + (size_t)(b * NN + n0 + n) * 8) = *(uint4*)h;
        } else {
#pragma unroll
            for (int r = 0; r < 8; r++) h[r] = o_s[8 + r][n];
            *(uint4*)(g_kt + (size_t)(b * NN + n0 + n) * 8) = *(uint4*)h;
        }
    }
    // ---- v + pad rows: g_vp[n][80], 10 uint4 per n-col ----
    for (int i = tid; i < 640; i += 128) {
        int n = i / 10, s = i % 10;
        __half h[8];
        if (s < 8) {
#pragma unroll
            for (int j = 0; j < 8; j++) h[j] = o_s[16 + s * 8 + j][n];
        } else if (s == 8) {
            h[0] = __float2half_rn(1.0f);                  // ones row (r=64)
#pragma unroll
            for (int j = 1; j < 8; j++) h[j] = __ushort_as_half(0);
        } else {
#pragma unroll
            for (int j = 0; j < 8; j++) h[j] = __ushort_as_half(0);
        }
        *(uint4*)(g_vp + (size_t)(b * NN + n0 + n) * MR + s * 8) = *(uint4*)h;
    }
}

// ---------------------------------------------------------------------------
// Attention main: CTA = (32 m-cols, batch, n-half). 4 warps, 1024 CTAs.
// FA2 identity (S^T C-frags = PV A-frags), exp in registers.
// Triple-buffered cp.async, ONE __syncthreads per tile:
//   wait<1> -> barrier -> issue prefetch(it+2) -> compute buf[it%3]
// ---------------------------------------------------------------------------
__global__ __launch_bounds__(128, 6) void attn_kernel()
{
    __shared__ __half k_s[BM][8];            // 0.5 KB
    __shared__ __half q_s[3][BN][8];         // 3 KB
    __shared__ __half v_s[3][BN][88];        // 33.8 KB (stride 176B: conflict-free)

    const int b  = blockIdx.y;
    const int m0 = blockIdx.x * BM;
    const int sp = blockIdx.z;
    const int s0 = sp * NHALF;
    const int tid = threadIdx.x;
    const int w = tid >> 5, lane = tid & 31, g = lane >> 2, tc = lane & 3;
    const int mt_ = w & 1;       // m-tile: cols mt_*16 .. +15
    const int rh  = w >> 1;      // r-half: rows rh*40 .. +39

    // ---- k tile ----
    if (tid < BM)
        *(uint4*)&k_s[tid][0] = *(const uint4*)(g_kt + (size_t)(b * NN + m0 + tid) * 8);

    // ---- prologue: prefetch tiles 0 and 1 ----
#pragma unroll
    for (int p = 0; p < 2; p++) {
        const int nn = s0 + p * BN;
        if (tid < BN)
            cpa16(&q_s[p][tid][0], g_qt + (size_t)(b * NN + nn + tid) * 8);
#pragma unroll
        for (int i = 0; i < 5; i++) {
            int e = tid + i * 128;
            int nl = e / 10, seg = e % 10;
            cpa16(&v_s[p][nl][seg * 8], g_vp + (size_t)(b * NN + nn + nl) * MR + seg * 8);
        }
        cpa_commit();
    }
    __syncthreads();   // k_s visible

    // A fragments for S^T (resident whole kernel)
    unsigned ka0, ka1;
    ldm_x2(ka0, ka1, smem_u32(&k_s[mt_ * 16 + (lane & 15)][0]));

    // O^T accumulators: m16 x (5 r8-tiles)
    float O[5][4];
#pragma unroll
    for (int rt = 0; rt < 5; rt++)
#pragma unroll
        for (int r = 0; r < 4; r++) O[rt][r] = 0.f;

    const float L2E = 1.44269504f;
    int cur = 0;

    for (int it = 0; it < NT; it++) {
        // ---- wait for tile it, fence all prior readers ----
        if (it == NT - 1) cpa_wait<0>(); else cpa_wait<1>();
        __syncthreads();

        // ---- issue prefetch of tile it+2 (buffer freed by the barrier) ----
        if (it + 2 < NT) {
            const int nxt = (cur + 2 >= 3) ? cur - 1 : cur + 2;
            const int nn = s0 + (it + 2) * BN;
            if (tid < BN)
                cpa16(&q_s[nxt][tid][0], g_qt + (size_t)(b * NN + nn + tid) * 8);
#pragma unroll
            for (int i = 0; i < 5; i++) {
                int e = tid + i * 128;
                int nl = e / 10, seg = e % 10;
                cpa16(&v_s[nxt][nl][seg * 8], g_vp + (size_t)(b * NN + nn + nl) * MR + seg * 8);
            }
            cpa_commit();
        }

        // ---- q B-fragments: 8 n8-tiles ----
        unsigned qb[8];
        ldm_x4(qb[0], qb[1], qb[2], qb[3], smem_u32(&q_s[cur][lane][0]));
        ldm_x4(qb[4], qb[5], qb[6], qb[7], smem_u32(&q_s[cur][32 + lane][0]));

        // ---- S^T + exp -> PV A-fragments (registers only) ----
        unsigned ea[4][4];
#pragma unroll
        for (int nt = 0; nt < 8; nt++) {
            float s[4] = {0.f, 0.f, 0.f, 0.f};
            mma_k8(s, ka0, ka1, qb[nt]);
            __half2 h01 = __floats2half2_rn(s[0] * L2E, s[1] * L2E);
            __half2 h23 = __floats2half2_rn(s[2] * L2E, s[3] * L2E);
            unsigned e01, e23;
            asm volatile("ex2.approx.f16x2 %0, %1;\n" : "=r"(e01) : "r"(*(unsigned*)&h01));
            asm volatile("ex2.approx.f16x2 %0, %1;\n" : "=r"(e23) : "r"(*(unsigned*)&h23));
            ea[nt >> 1][(nt & 1) * 2]     = e01;
            ea[nt >> 1][(nt & 1) * 2 + 1] = e23;
        }

        // ---- O^T += E^T[m16, n64] @ V'^T[n64, r40] ----
#pragma unroll
        for (int ks = 0; ks < 4; ks++) {
            unsigned vb[10];
            ldm_x4_t(vb[0], vb[1], vb[2], vb[3],
                     smem_u32(&v_s[cur][ks * 16 + (lane & 15)][rh * 40 + 8 * (lane >> 4)]));
            ldm_x4_t(vb[4], vb[5], vb[6], vb[7],
                     smem_u32(&v_s[cur][ks * 16 + (lane & 15)][rh * 40 + 16 + 8 * (lane >> 4)]));
            ldm_x2_t(vb[8], vb[9],
                     smem_u32(&v_s[cur][ks * 16 + (lane & 15)][rh * 40 + 32]));
#pragma unroll
            for (int rt = 0; rt < 5; rt++)
                mma_k16(O[rt], ea[ks][0], ea[ks][1], ea[ks][2], ea[ks][3],
                        vb[2 * rt], vb[2 * rt + 1]);
        }

        cur = (cur + 1 == 3) ? 0 : cur + 1;
    }

    // ---- write fp32 partials (transposed): P[r][m] ----
    float* P = g_part + ((size_t)(sp * BB + b) * 65) * NN + m0;
    const int m = mt_ * 16 + g;
#pragma unroll
    for (int rt = 0; rt < 5; rt++) {
        int r = rh * 40 + rt * 8 + tc * 2;
        if (r < 64) {
            P[(size_t)r * NN + m]           = O[rt][0];
            P[(size_t)(r + 1) * NN + m]     = O[rt][1];
            P[(size_t)r * NN + m + 8]       = O[rt][2];
            P[(size_t)(r + 1) * NN + m + 8] = O[rt][3];
        } else if (r == 64) {   // denominator row
            P[(size_t)64 * NN + m]     = O[rt][0];
            P[(size_t)64 * NN + m + 8] = O[rt][2];
        }
    }
}

// ---------------------------------------------------------------------------
// Combine: out = gamma * (O0+O1)/(d0+d1) + x
// ---------------------------------------------------------------------------
__global__ __launch_bounds__(256) void combine_kernel(
    const float* __restrict__ x,
    const float* __restrict__ gamma,
    float* __restrict__ out)
{
    const int idx = blockIdx.x * 256 + threadIdx.x;
    const int e = idx * 4;
    const int b = e >> 18;
    const int c = (e >> 12) & 63;
    const int m = e & (NN - 1);

    const float* P0 = g_part + ((size_t)(0 * BB + b) * 65) * NN;
    const float* P1 = g_part + ((size_t)(1 * BB + b) * 65) * NN;

    float4 n0 = *(const float4*)(P0 + (size_t)c * NN + m);
    float4 n1 = *(const float4*)(P1 + (size_t)c * NN + m);
    float4 d0 = *(const float4*)(P0 + (size_t)64 * NN + m);
    float4 d1 = *(const float4*)(P1 + (size_t)64 * NN + m);
    float4 xv = *(const float4*)(x + (size_t)(b * CC + c) * NN + m);
    const float gam = *gamma;

    float4 o;
    o.x = gam * (n0.x + n1.x) / (d0.x + d1.x) + xv.x;
    o.y = gam * (n0.y + n1.y) / (d0.y + d1.y) + xv.y;
    o.z = gam * (n0.z + n1.z) / (d0.z + d1.z) + xv.z;
    o.w = gam * (n0.w + n1.w) / (d0.w + d1.w) + xv.w;
    *(float4*)(out + (size_t)(b * CC + c) * NN + m) = o;
}

// ---------------------------------------------------------------------------
extern "C" void kernel_launch(void* const* d_in, const int* in_sizes, int n_in,
                              void* d_out, int out_size)
{
    const float* x     = (const float*)d_in[0];
    const float* Wq    = (const float*)d_in[1];
    const float* Wk    = (const float*)d_in[2];
    const float* Wv    = (const float*)d_in[3];
    const float* gamma = (const float*)d_in[4];
    float* out = (float*)d_out;

    proj_kernel<<<(BB * NN) / 64, 128>>>(x, Wq, Wk, Wv);
    attn_kernel<<<dim3(NN / BM, BB, NSPLIT), 128>>>();
    combine_kernel<<<(BB * CC * NN) / (256 * 4), 256>>>(x, gamma, out);
}